// round 2
// baseline (speedup 1.0000x reference)
#include <cuda_runtime.h>
#include <cstdint>

// ---------------------------------------------------------------------------
// EmbeddingLoss: B=4, E=16, S=96, K=32 clusters.
//   k_prep : BCE partials + per-label counts + packed seg[] (u8, 255 = masked out)
//   k_bins : per-(b,e,chunk) segmented sum & sumsq via thread-private smem bins
//            (interleaved layout -> conflict-free LDS.64/STS.64 RMW)
//   k_final: deterministic reduction of partials + centers/internal/hinge/reg + BCE
// No device allocation; scratch lives in __device__ globals. All reductions are
// fixed-order (no float atomics) -> bit-deterministic across graph replays.
// ---------------------------------------------------------------------------

constexpr int B_   = 4;
constexpr int E_   = 16;
constexpr int N_   = 96 * 96 * 96;   // 884736 voxels per batch
constexpr int N4_  = N_ / 4;         // 221184 float4 groups
constexpr int KC   = 32;             // cluster bins
constexpr int CH0  = 64;             // prep chunks per batch
constexpr int CHA  = 32;             // binning chunks per (b,e)
constexpr int C4_0 = N4_ / CH0;      // 3456
constexpr int C4_A = N4_ / CHA;      // 6912

// scratch (written fully each launch before being read -> no zero-init needed)
__device__ unsigned char g_seg[B_ * N_];                 // 3.5 MB, L2-resident
__device__ float2        g_pSum[B_ * E_ * CHA * KC];     // [b][e][ch][k] (sum, sumsq)
__device__ float         g_pCnt[B_ * CH0 * KC];          // [b][ch0][k]
__device__ float         g_pBce[B_ * CH0];

// ---------------------------------------------------------------------------
// Kernel 0: prep. grid = B*CH0 blocks, 256 threads.
// ---------------------------------------------------------------------------
__global__ __launch_bounds__(256) void k_prep(const float* __restrict__ masks,
                                              const int*   __restrict__ lbl,
                                              const float* __restrict__ tmask)
{
    __shared__ float sCnt[256 * 33];   // per-thread private count bins (pad 33)
    __shared__ float sRedC[8 * 32];
    __shared__ float sRedB[8];

    const int tid = threadIdx.x;
    const int bid = blockIdx.x;
    const int b   = bid / CH0;
    const int ch  = bid % CH0;
    const long base4 = (long)b * N4_ + (long)ch * C4_0;

    float* mybin = &sCnt[tid * 33];
#pragma unroll
    for (int k = 0; k < KC; k++) mybin[k] = 0.f;

    const int4*   lv = (const int4*)lbl    + base4;
    const float4* tv = (const float4*)tmask + base4;
    const float4* xv = (const float4*)masks + base4;
    uchar4*       sv = (uchar4*)g_seg + base4;

    float bce = 0.f;
    for (int i = tid; i < C4_0; i += 256) {
        int4   L = lv[i];
        float4 T = tv[i];
        float4 X = xv[i];
        uchar4 s;
#define PREP1(comp)                                                           \
        {                                                                     \
            bool m = (T.comp != 0.f) && ((unsigned)L.comp < 32u);             \
            s.comp = m ? (unsigned char)L.comp : (unsigned char)255;          \
            if (m) mybin[L.comp] += 1.f;                                      \
            float a = fabsf(X.comp);                                          \
            bce += fmaxf(X.comp, 0.f) - X.comp * T.comp + log1pf(__expf(-a)); \
        }
        PREP1(x) PREP1(y) PREP1(z) PREP1(w)
#undef PREP1
        sv[i] = s;
    }
    __syncthreads();

    const int lane = tid & 31, w = tid >> 5;
    // per-warp reduce counts over its 32 threads (conflict-free: consecutive k)
    float acc = 0.f;
#pragma unroll 8
    for (int t = 0; t < 32; t++) acc += sCnt[(w * 32 + t) * 33 + lane];
    sRedC[w * 32 + lane] = acc;

    float bb = bce;
#pragma unroll
    for (int o = 16; o; o >>= 1) bb += __shfl_xor_sync(0xffffffffu, bb, o);
    if (lane == 0) sRedB[w] = bb;
    __syncthreads();

    if (w == 0) {
        float tot = 0.f;
#pragma unroll
        for (int q = 0; q < 8; q++) tot += sRedC[q * 32 + lane];
        g_pCnt[(b * CH0 + ch) * KC + lane] = tot;
        if (lane == 0) {
            float bt = 0.f;
#pragma unroll
            for (int q = 0; q < 8; q++) bt += sRedB[q];
            g_pBce[bid] = bt;
        }
    }
}

// ---------------------------------------------------------------------------
// Kernel A: segmented sum/sumsq. grid = B*E*CHA blocks, 128 threads.
// Each thread owns 32 float2 bins in shared, INTERLEAVED as bins[k*128 + tid]:
// the RMW bank is (tid*2) mod 32, so every 16-lane LDS.64 phase covers all 32
// banks exactly once -> conflict-free regardless of label distribution.
// ---------------------------------------------------------------------------
__global__ __launch_bounds__(128) void k_bins(const float* __restrict__ emb)
{
    __shared__ float2 bins[KC * 128];  // 32 KB, [k][tid]
    __shared__ float2 sRed[4 * 32];

    const int tid = threadIdx.x;
    const int bid = blockIdx.x;
    const int ch  = bid & (CHA - 1);
    const int be  = bid >> 5;          // b*16 + e
    const int b   = be >> 4;

#pragma unroll
    for (int k = 0; k < KC; k++) bins[k * 128 + tid] = make_float2(0.f, 0.f);

    const float4* ev = (const float4*)emb + (long)be * N4_ + (long)ch * C4_A;
    const uchar4* sv = (const uchar4*)g_seg + (long)b * N4_ + (long)ch * C4_A;

    for (int i = tid; i < C4_A; i += 128) {
        float4 v = ev[i];
        uchar4 s = sv[i];
#define ACC1(sc, vc)                                                   \
        if (s.sc != 255) {                                             \
            float2 a = bins[(int)s.sc * 128 + tid];                    \
            a.x += v.vc; a.y += v.vc * v.vc;                           \
            bins[(int)s.sc * 128 + tid] = a;                           \
        }
        ACC1(x, x) ACC1(y, y) ACC1(z, z) ACC1(w, w)
#undef ACC1
    }
    __syncthreads();

    const int lane = tid & 31, w = tid >> 5;
    // warp w sums bin k=lane over threads t in [w*32, w*32+32)
    float2 acc = make_float2(0.f, 0.f);
#pragma unroll 8
    for (int t = 0; t < 32; t++) {
        float2 x = bins[lane * 128 + (w * 32 + t)];
        acc.x += x.x; acc.y += x.y;
    }
    sRed[w * 32 + lane] = acc;
    __syncthreads();

    if (w == 0) {
        float2 tot = make_float2(0.f, 0.f);
#pragma unroll
        for (int q = 0; q < 4; q++) {
            float2 x = sRed[q * 32 + lane];
            tot.x += x.x; tot.y += x.y;
        }
        g_pSum[(long)bid * KC + lane] = tot;   // bid == ((b*16+e)*CHA+ch)
    }
}

// ---------------------------------------------------------------------------
// Kernel B: finalize. 1 block, 512 threads.
// ---------------------------------------------------------------------------
__global__ __launch_bounds__(512) void k_final(float* __restrict__ out)
{
    __shared__ float2 sSum[B_ * E_ * KC];     // [b][e][k]  16 KB
    __shared__ float  sCntP[B_ * 4 * KC];     // 2 KB
    __shared__ float  sCent[B_][KC][E_];      // 8 KB
    __shared__ float  sRes[B_][3];
    __shared__ float  sBce;

    const int tid  = threadIdx.x;
    const int b    = tid >> 7;
    const int sub  = tid & 127;
    const int k    = sub & 31;
    const int part = sub >> 5;                // 0..3

    // reduce channel sums over chunks (each (b,e,k) owned by one thread)
#pragma unroll
    for (int i = 0; i < 4; i++) {
        const int e = part * 4 + i;
        float2 acc = make_float2(0.f, 0.f);
        const float2* p = &g_pSum[(long)((b * E_ + e) * CHA) * KC + k];
        for (int ch = 0; ch < CHA; ch++) {
            float2 x = p[(long)ch * KC];
            acc.x += x.x; acc.y += x.y;
        }
        sSum[(b * E_ + e) * KC + k] = acc;
    }
    // reduce counts
    {
        float c = 0.f;
        for (int c0 = part * 16; c0 < part * 16 + 16; c0++)
            c += g_pCnt[(b * CH0 + c0) * KC + k];
        sCntP[(b * 4 + part) * KC + k] = c;
    }
    // reduce BCE (warp 0)
    if (tid < 32) {
        float a = 0.f;
        for (int q = tid; q < B_ * CH0; q += 32) a += g_pBce[q];
#pragma unroll
        for (int o = 16; o; o >>= 1) a += __shfl_xor_sync(0xffffffffu, a, o);
        if (tid == 0) sBce = a;
    }
    __syncthreads();

    if (tid < 128) {
        const int bb   = tid >> 5;
        const int lane = tid & 31;
        float cnt = sCntP[(bb * 4 + 0) * KC + lane] + sCntP[(bb * 4 + 1) * KC + lane]
                  + sCntP[(bb * 4 + 2) * KC + lane] + sCntP[(bb * 4 + 3) * KC + lane];
        float safe = fmaxf(cnt, 1.f);
        float center[E_];
        float sq = 0.f, cs = 0.f;
#pragma unroll
        for (int e = 0; e < E_; e++) {
            float2 s = sSum[(bb * E_ + e) * KC + lane];
            float c = s.x / safe;
            center[e] = c;
            cs += c * c;
            sq += s.y;
        }
        bool fg = (cnt > 0.f) && (lane > 0);
        unsigned fgm = __ballot_sync(0xffffffffu, fg);
        float C = (float)__popc(fgm);
#pragma unroll
        for (int e = 0; e < E_; e++) sCent[bb][lane][e] = center[e];
        __syncwarp();

        float internal_j = sq / safe - cs;
        float vi = fg ? internal_j : 0.f;
        float vr = fg ? sqrtf(cs) : 0.f;
        float hs = 0.f;
        for (int j = 0; j < KC; j++) {
            if ((fgm >> j) & 1u) {
                float d2 = 0.f;
#pragma unroll
                for (int e = 0; e < E_; e++) {
                    float d = center[e] - sCent[bb][j][e];
                    d2 += d * d;
                }
                if (fg && j != lane) {
                    float d = sqrtf(d2);
                    float h = fmaxf(2.f * 1.5f - d, 0.f);
                    hs += h * h;
                }
            }
        }
#pragma unroll
        for (int o = 16; o; o >>= 1) {
            vi += __shfl_xor_sync(0xffffffffu, vi, o);
            vr += __shfl_xor_sync(0xffffffffu, vr, o);
            hs += __shfl_xor_sync(0xffffffffu, hs, o);
        }
        if (lane == 0) {
            float Cs = fmaxf(C, 1.f);
            sRes[bb][0] = (C >= 1.f) ? vi / Cs : 0.f;                          // internal
            sRes[bb][1] = (C >= 2.f) ? hs / fmaxf(C * (C - 1.f), 1.f) : 0.f;    // external
            sRes[bb][2] = (C >= 1.f) ? vr / Cs : 0.f;                          // reg
        }
    }
    __syncthreads();

    if (tid == 0) {
        float mi = 0.f, me = 0.f, mr = 0.f;
#pragma unroll
        for (int q = 0; q < B_; q++) { mi += sRes[q][0]; me += sRes[q][1]; mr += sRes[q][2]; }
        mi *= 0.25f; me *= 0.25f; mr *= 0.25f;
        float bce = sBce / (float)((long)B_ * N_);
        // total = ALPHA*internal + BETA*external + GAMMA + reg + bce
        out[0] = 1.0f * mi + 1.0f * me + 0.001f + mr + bce;
    }
}

// ---------------------------------------------------------------------------
extern "C" void kernel_launch(void* const* d_in, const int* in_sizes, int n_in,
                              void* d_out, int out_size)
{
    (void)in_sizes; (void)n_in; (void)out_size;
    const float* emb   = (const float*)d_in[0];  // [4,16,96^3] f32
    const float* masks = (const float*)d_in[1];  // [4,1,96^3]  f32 logits
    const int*   lbl   = (const int*)d_in[2];    // [4,1,96^3]  int32 labels
    const float* tmask = (const float*)d_in[3];  // [4,1,96^3]  f32 0/1
    float* out = (float*)d_out;

    k_prep<<<B_ * CH0, 256>>>(masks, lbl, tmask);
    k_bins<<<B_ * E_ * CHA, 128>>>(emb);
    k_final<<<1, 512>>>(out);
}

// round 3
// speedup vs baseline: 1.2271x; 1.2271x over previous
#include <cuda_runtime.h>
#include <cstdint>

// ---------------------------------------------------------------------------
// EmbeddingLoss: B=4, E=16, S=96, K=32 clusters.
//   k_prep : BCE partials + per-label u8 counts + packed seg[] (255 = masked out)
//   k_bins : per-(b,e,chunk) segmented sum & sumsq via thread-private smem bins
//   k_final: deterministic reduction + centers/internal/hinge/reg + BCE
// No device allocation; scratch in __device__ globals. Fixed-order reductions
// (no float atomics) -> bit-deterministic across graph replays.
// ---------------------------------------------------------------------------

constexpr int B_   = 4;
constexpr int E_   = 16;
constexpr int N_   = 96 * 96 * 96;   // 884736 voxels per batch
constexpr int N4_  = N_ / 4;         // 221184 float4 groups
constexpr int KC   = 32;

constexpr int CH0   = 256;           // prep chunks per batch
constexpr int C4_0  = N4_ / CH0;     // 864
constexpr int T0    = 96;            // prep threads (864 = 96*9)
constexpr int IT0   = C4_0 / T0;     // 9

constexpr int CHA   = 32;            // binning chunks per (b,e)
constexpr int C4_A  = N4_ / CHA;     // 6912
constexpr int TA    = 128;
constexpr int ITA   = C4_A / TA;     // 54 (compile-time -> full unroll, MLP)

// scratch (fully written each launch before read -> no zero-init needed)
__device__ unsigned char g_seg[B_ * N_];                 // 3.5 MB, L2-resident
__device__ float2        g_pSum[B_ * E_ * CHA * KC];     // [be][ch][k] (sum, sumsq)
__device__ float         g_pCnt[B_ * CH0 * KC];          // [b][ch0][k]
__device__ float         g_pBce[B_ * CH0];

// ---------------------------------------------------------------------------
// Kernel 0: prep. grid = B*CH0 = 1024 blocks, 96 threads, 9 iters/thread.
// ---------------------------------------------------------------------------
__global__ __launch_bounds__(T0) void k_prep(const float* __restrict__ masks,
                                             const int*   __restrict__ lbl,
                                             const float* __restrict__ tmask)
{
    __shared__ unsigned char sCnt[T0 * 33];   // u8 per-thread bins (max 36/bin)
    __shared__ float sRedC[3 * 32];
    __shared__ float sRedB[3];

    const int tid = threadIdx.x;
    const int bid = blockIdx.x;
    const int b   = bid >> 8;
    const int ch  = bid & 255;
    const long base4 = (long)b * N4_ + (long)ch * C4_0;

    unsigned char* mybin = &sCnt[tid * 33];
#pragma unroll
    for (int k = 0; k < KC; k++) mybin[k] = 0;

    const int4*   lv = (const int4*)lbl     + base4;
    const float4* tv = (const float4*)tmask + base4;
    const float4* xv = (const float4*)masks + base4;
    uchar4*       sv = (uchar4*)g_seg + base4;

    float bce = 0.f;
#pragma unroll
    for (int it = 0; it < IT0; it++) {
        const int i = tid + it * T0;
        int4   L = lv[i];
        float4 T = tv[i];
        float4 X = xv[i];
        uchar4 s;
#define PREP1(comp)                                                            \
        {                                                                      \
            bool m = (T.comp != 0.f) && ((unsigned)L.comp < 32u);              \
            s.comp = m ? (unsigned char)L.comp : (unsigned char)255;           \
            if (m) mybin[L.comp] = mybin[L.comp] + 1;                          \
            float a = fabsf(X.comp);                                           \
            bce += fmaxf(X.comp, 0.f) - X.comp * T.comp                        \
                 + __logf(1.f + __expf(-a));                                   \
        }
        PREP1(x) PREP1(y) PREP1(z) PREP1(w)
#undef PREP1
        sv[i] = s;
    }
    __syncthreads();

    const int lane = tid & 31, w = tid >> 5;   // 3 warps
    float acc = 0.f;
#pragma unroll 8
    for (int t = 0; t < 32; t++) acc += (float)sCnt[(w * 32 + t) * 33 + lane];
    sRedC[w * 32 + lane] = acc;

    float bb = bce;
#pragma unroll
    for (int o = 16; o; o >>= 1) bb += __shfl_xor_sync(0xffffffffu, bb, o);
    if (lane == 0) sRedB[w] = bb;
    __syncthreads();

    if (w == 0) {
        float tot = sRedC[lane] + sRedC[32 + lane] + sRedC[64 + lane];
        g_pCnt[(b * CH0 + ch) * KC + lane] = tot;
        if (lane == 0) g_pBce[bid] = sRedB[0] + sRedB[1] + sRedB[2];
    }
}

// ---------------------------------------------------------------------------
// Kernel A: segmented sum/sumsq. grid = CHA * 64 blocks, 128 threads.
// Block order: 64 consecutive blocks share one seg chunk (L2 reuse of the
// 16x-read seg). Thread-private interleaved bins bins[k*128+tid]:
// bank = (tid*2) mod 32 -> conflict-free LDS.64/STS.64 RMW regardless of label.
// Compile-time 54-iteration loop -> full unroll -> high LDG MLP.
// ---------------------------------------------------------------------------
__global__ __launch_bounds__(TA) void k_bins(const float* __restrict__ emb)
{
    __shared__ float2 bins[KC * TA];  // exactly 32 KB

    const int tid = threadIdx.x;
    const int bid = blockIdx.x;
    const int ch  = bid >> 6;          // 0..CHA-1 (same for 64 consecutive bids)
    const int be  = bid & 63;          // b*16 + e
    const int b   = be >> 4;

#pragma unroll
    for (int k = 0; k < KC; k++) bins[k * TA + tid] = make_float2(0.f, 0.f);

    const float4* ev = (const float4*)emb   + (long)be * N4_ + (long)ch * C4_A;
    const uchar4* sv = (const uchar4*)g_seg + (long)b  * N4_ + (long)ch * C4_A;

#pragma unroll 6
    for (int it = 0; it < ITA; it++) {
        const int i = tid + it * TA;
        float4 v = __ldcs(&ev[i]);     // streaming: don't evict seg from L2
        uchar4 s = __ldg(&sv[i]);
#define ACC1(sc, vc)                                                   \
        if (s.sc != 255) {                                             \
            float2 a = bins[(int)s.sc * TA + tid];                     \
            a.x += v.vc; a.y += v.vc * v.vc;                           \
            bins[(int)s.sc * TA + tid] = a;                            \
        }
        ACC1(x, x) ACC1(y, y) ACC1(z, z) ACC1(w, w)
#undef ACC1
    }
    __syncthreads();

    const int lane = tid & 31, w = tid >> 5;
    // warp w sums bin k=lane over thread columns [w*32, w*32+32)
    float2 acc = make_float2(0.f, 0.f);
#pragma unroll 8
    for (int t = 0; t < 32; t++) {
        float2 x = bins[lane * TA + (w * 32 + t)];
        acc.x += x.x; acc.y += x.y;
    }
    __syncthreads();                   // all reads done -> safe to reuse bins
    bins[w * 32 + lane] = acc;         // slots 0..127 (row k=0, already consumed)
    __syncthreads();

    if (w == 0) {
        float2 tot = make_float2(0.f, 0.f);
#pragma unroll
        for (int q = 0; q < 4; q++) {
            float2 x = bins[q * 32 + lane];
            tot.x += x.x; tot.y += x.y;
        }
        g_pSum[(long)(be * CHA + ch) * KC + lane] = tot;
    }
}

// ---------------------------------------------------------------------------
// Kernel B: finalize. 1 block, 512 threads.
// ---------------------------------------------------------------------------
__global__ __launch_bounds__(512) void k_final(float* __restrict__ out)
{
    __shared__ float2 sSum[B_ * E_ * KC];     // [b][e][k]  16 KB
    __shared__ float  sCntP[B_ * 4 * KC];     // 2 KB
    __shared__ float  sCent[B_][KC][E_];      // 8 KB
    __shared__ float  sRes[B_][3];
    __shared__ float  sBce;

    const int tid  = threadIdx.x;
    const int b    = tid >> 7;
    const int sub  = tid & 127;
    const int k    = sub & 31;
    const int part = sub >> 5;                // 0..3

    // reduce channel sums over chunks (each (b,e,k) owned by one thread)
#pragma unroll
    for (int i = 0; i < 4; i++) {
        const int e = part * 4 + i;
        float2 acc = make_float2(0.f, 0.f);
        const float2* p = &g_pSum[(long)((b * E_ + e) * CHA) * KC + k];
#pragma unroll 8
        for (int ch = 0; ch < CHA; ch++) {
            float2 x = p[(long)ch * KC];
            acc.x += x.x; acc.y += x.y;
        }
        sSum[(b * E_ + e) * KC + k] = acc;
    }
    // reduce counts: part covers CH0/4 = 64 chunks
    {
        float c = 0.f;
#pragma unroll 8
        for (int c0 = part * 64; c0 < part * 64 + 64; c0++)
            c += g_pCnt[(b * CH0 + c0) * KC + k];
        sCntP[(b * 4 + part) * KC + k] = c;
    }
    // reduce BCE (warp 0): B*CH0 = 1024 partials
    if (tid < 32) {
        float a = 0.f;
#pragma unroll 8
        for (int q = tid; q < B_ * CH0; q += 32) a += g_pBce[q];
#pragma unroll
        for (int o = 16; o; o >>= 1) a += __shfl_xor_sync(0xffffffffu, a, o);
        if (tid == 0) sBce = a;
    }
    __syncthreads();

    if (tid < 128) {
        const int bb   = tid >> 5;
        const int lane = tid & 31;
        float cnt = sCntP[(bb * 4 + 0) * KC + lane] + sCntP[(bb * 4 + 1) * KC + lane]
                  + sCntP[(bb * 4 + 2) * KC + lane] + sCntP[(bb * 4 + 3) * KC + lane];
        float safe = fmaxf(cnt, 1.f);
        float center[E_];
        float sq = 0.f, cs = 0.f;
#pragma unroll
        for (int e = 0; e < E_; e++) {
            float2 s = sSum[(bb * E_ + e) * KC + lane];
            float c = s.x / safe;
            center[e] = c;
            cs += c * c;
            sq += s.y;
        }
        bool fg = (cnt > 0.f) && (lane > 0);
        unsigned fgm = __ballot_sync(0xffffffffu, fg);
        float C = (float)__popc(fgm);
#pragma unroll
        for (int e = 0; e < E_; e++) sCent[bb][lane][e] = center[e];
        __syncwarp();

        float internal_j = sq / safe - cs;
        float vi = fg ? internal_j : 0.f;
        float vr = fg ? sqrtf(cs) : 0.f;
        float hs = 0.f;
        for (int j = 0; j < KC; j++) {
            if ((fgm >> j) & 1u) {
                float d2 = 0.f;
#pragma unroll
                for (int e = 0; e < E_; e++) {
                    float d = center[e] - sCent[bb][j][e];
                    d2 += d * d;
                }
                if (fg && j != lane) {
                    float d = sqrtf(d2);
                    float h = fmaxf(2.f * 1.5f - d, 0.f);
                    hs += h * h;
                }
            }
        }
#pragma unroll
        for (int o = 16; o; o >>= 1) {
            vi += __shfl_xor_sync(0xffffffffu, vi, o);
            vr += __shfl_xor_sync(0xffffffffu, vr, o);
            hs += __shfl_xor_sync(0xffffffffu, hs, o);
        }
        if (lane == 0) {
            float Cs = fmaxf(C, 1.f);
            sRes[bb][0] = (C >= 1.f) ? vi / Cs : 0.f;                           // internal
            sRes[bb][1] = (C >= 2.f) ? hs / fmaxf(C * (C - 1.f), 1.f) : 0.f;     // external
            sRes[bb][2] = (C >= 1.f) ? vr / Cs : 0.f;                           // reg
        }
    }
    __syncthreads();

    if (tid == 0) {
        float mi = 0.f, me = 0.f, mr = 0.f;
#pragma unroll
        for (int q = 0; q < B_; q++) { mi += sRes[q][0]; me += sRes[q][1]; mr += sRes[q][2]; }
        mi *= 0.25f; me *= 0.25f; mr *= 0.25f;
        float bce = sBce / (float)((long)B_ * N_);
        // total = ALPHA*internal + BETA*external + GAMMA + reg + bce
        out[0] = 1.0f * mi + 1.0f * me + 0.001f + mr + bce;
    }
}

// ---------------------------------------------------------------------------
extern "C" void kernel_launch(void* const* d_in, const int* in_sizes, int n_in,
                              void* d_out, int out_size)
{
    (void)in_sizes; (void)n_in; (void)out_size;
    const float* emb   = (const float*)d_in[0];  // [4,16,96^3] f32
    const float* masks = (const float*)d_in[1];  // [4,1,96^3]  f32 logits
    const int*   lbl   = (const int*)d_in[2];    // [4,1,96^3]  int32 labels
    const float* tmask = (const float*)d_in[3];  // [4,1,96^3]  f32 0/1
    float* out = (float*)d_out;

    k_prep <<<B_ * CH0,   T0>>>(masks, lbl, tmask);
    k_bins <<<CHA * 64,   TA>>>(emb);
    k_final<<<1, 512>>>(out);
}